// round 2
// baseline (speedup 1.0000x reference)
#include <cuda_runtime.h>
#include <cstdint>
#include <cub/cub.cuh>

// Problem constants (fixed shapes from reference)
#define B_BATCH 4
#define C_CLS   19
#define HW      (512 * 512)            // 262144
#define P_PIX   (B_BATCH * HW)         // 1048576
#define TOTAL   (P_PIX * C_CLS)        // 19922944

#define TILE            4096
#define TILES_PER_CLASS (P_PIX / TILE) // 256
#define NUM_TILES       (TILES_PER_CLASS * C_CLS) // 4864

// Scratch: __device__ globals (no allocation allowed in kernel_launch)
__device__ __align__(16) uint32_t g_keysA[TOTAL];
__device__ __align__(16) uint32_t g_keysB[TOTAL];
__device__ __align__(16) unsigned char g_sort_temp[64u << 20]; // 64 MB
__device__ uint32_t g_tileSums[NUM_TILES];
__device__ uint32_t g_tileOffsets[NUM_TILES];
__device__ uint32_t g_segTotal[C_CLS];
__device__ double   g_loss;

// ---------------------------------------------------------------------------
// Kernel 1: fused softmax + key build.
// key = (class << 27) | (err_bits[29:4] << 1) | gt
// err in [0,1] -> fp32 bits <= 0x3F800000 (30 bits); keep top 26 bits.
// Ties/truncation perturb the loss by <=~1e-6 (far below 1e-3 tolerance):
// within a run of equal errors the contribution telescopes and depends only
// on the gt-count in the run, not the order.
// NOTE: targets are int32 on device (JAX x64 disabled -> int64 request
// silently materializes as int32).
// ---------------------------------------------------------------------------
__global__ void build_keys_kernel(const float* __restrict__ logits,
                                  const int* __restrict__ targets,
                                  uint32_t* __restrict__ keys) {
    int p = blockIdx.x * blockDim.x + threadIdx.x;
    if (p >= P_PIX) return;
    int b  = p >> 18;          // p / HW
    int hw = p & (HW - 1);
    const float* base = logits + (size_t)b * C_CLS * HW + hw;

    float l[C_CLS];
    float m = -1e30f;
#pragma unroll
    for (int c = 0; c < C_CLS; c++) {
        l[c] = base[(size_t)c * HW];
        m = fmaxf(m, l[c]);
    }
    float s = 0.0f;
#pragma unroll
    for (int c = 0; c < C_CLS; c++) {
        l[c] = __expf(l[c] - m);
        s += l[c];
    }
    float inv = 1.0f / s;
    int t = targets[p];
#pragma unroll
    for (int c = 0; c < C_CLS; c++) {
        float pr = l[c] * inv;
        uint32_t gt = (t == c) ? 1u : 0u;
        float err = gt ? (1.0f - pr) : pr;
        uint32_t bits = __float_as_uint(err);       // err >= 0 -> monotone bits
        uint32_t key = ((uint32_t)c << 27) | ((bits >> 4) << 1) | gt;
        keys[(size_t)c * P_PIX + p] = key;
    }
}

// ---------------------------------------------------------------------------
// Kernel 2 (after sort): per-tile gt-bit sums. One block (256 thr) per 4096-key
// tile, 16 keys per thread (vectorized uint4 loads).
// ---------------------------------------------------------------------------
__global__ void tile_sums_kernel(const uint32_t* __restrict__ keys) {
    size_t base = (size_t)blockIdx.x * TILE + (size_t)threadIdx.x * 16;
    const uint4* kp = (const uint4*)(keys + base);
    uint32_t s = 0;
#pragma unroll
    for (int j = 0; j < 4; j++) {
        uint4 v = kp[j];
        s += (v.x & 1u) + (v.y & 1u) + (v.z & 1u) + (v.w & 1u);
    }
#pragma unroll
    for (int o = 16; o > 0; o >>= 1) s += __shfl_down_sync(0xFFFFFFFFu, s, o);
    __shared__ uint32_t ws[8];
    if ((threadIdx.x & 31) == 0) ws[threadIdx.x >> 5] = s;
    __syncthreads();
    if (threadIdx.x < 8) {
        s = ws[threadIdx.x];
#pragma unroll
        for (int o = 4; o > 0; o >>= 1) s += __shfl_down_sync(0xFFu, s, o);
        if (threadIdx.x == 0) g_tileSums[blockIdx.x] = s;
    }
}

// ---------------------------------------------------------------------------
// Kernel 3: per-class exclusive scan of the 256 tile sums (one block/class).
// ---------------------------------------------------------------------------
__global__ void scan_tiles_kernel() {
    typedef cub::BlockScan<uint32_t, 256> BS;
    __shared__ typename BS::TempStorage ts;
    int base = blockIdx.x * TILES_PER_CLASS;
    uint32_t v = g_tileSums[base + threadIdx.x];
    uint32_t ex, tot;
    BS(ts).ExclusiveSum(v, ex, tot);
    g_tileOffsets[base + threadIdx.x] = ex;
    if (threadIdx.x == 0) g_segTotal[blockIdx.x] = tot;
}

// ---------------------------------------------------------------------------
// Kernel 4: evaluate Lovasz terms with the cancellation-free closed form.
//   gt=1: d_i = 1/U,   gt=0: d_i = a / (U*(U+1)),  with
//   a = n - CS_{i-1},  U = n + i - CS_{i-1}   (i = 0-based index in segment)
// ---------------------------------------------------------------------------
__global__ void loss_kernel(const uint32_t* __restrict__ keys) {
    typedef cub::BlockScan<uint32_t, 256> BS;
    __shared__ typename BS::TempStorage ts;
    __shared__ float red[256];

    int tile = blockIdx.x;
    int seg  = tile >> 8;                // tile / TILES_PER_CLASS
    uint32_t n = g_segTotal[seg];

    size_t base = (size_t)tile * TILE + (size_t)threadIdx.x * 16;
    uint32_t k[16];
    const uint4* kp = (const uint4*)(keys + base);
#pragma unroll
    for (int j = 0; j < 4; j++) {
        uint4 v = kp[j];
        k[j * 4 + 0] = v.x; k[j * 4 + 1] = v.y;
        k[j * 4 + 2] = v.z; k[j * 4 + 3] = v.w;
    }
    uint32_t localSum = 0;
#pragma unroll
    for (int j = 0; j < 16; j++) localSum += k[j] & 1u;

    uint32_t thrOff;
    BS(ts).ExclusiveSum(localSum, thrOff);

    uint32_t cs = g_tileOffsets[tile] + thrOff;          // exclusive CS before elem 0
    uint32_t ibase = (uint32_t)(tile & 255) * TILE + (uint32_t)threadIdx.x * 16;

    float acc = 0.0f;
#pragma unroll
    for (int j = 0; j < 16; j++) {
        uint32_t key = k[j];
        uint32_t gt = key & 1u;
        cs += gt;                                        // inclusive CS_i
        uint32_t i = ibase + (uint32_t)j;
        float e = __uint_as_float(((key >> 1) & 0x3FFFFFFu) << 4);
        float d;
        if (n == 0u) {
            d = (i == 0u) ? 1.0f : 0.0f;
        } else {
            float U = (float)(n + i + gt - cs);          // = n + i - CS_{i-1}
            if (gt) {
                d = 1.0f / U;
            } else {
                float a = (float)(n - cs);               // = n - CS_{i-1}
                d = a / (U * (U + 1.0f));
            }
        }
        acc += e * d;
    }

    red[threadIdx.x] = acc;
    __syncthreads();
#pragma unroll
    for (int o = 128; o > 0; o >>= 1) {
        if (threadIdx.x < o) red[threadIdx.x] += red[threadIdx.x + o];
        __syncthreads();
    }
    if (threadIdx.x == 0) atomicAdd(&g_loss, (double)red[0]);
}

__global__ void finalize_kernel(float* __restrict__ out) {
    out[0] = (float)(g_loss / (double)C_CLS);
}

// ---------------------------------------------------------------------------
// Host launcher (graph-capturable; no allocation, no sync)
// ---------------------------------------------------------------------------
extern "C" void kernel_launch(void* const* d_in, const int* in_sizes, int n_in,
                              void* d_out, int out_size) {
    const float* logits = (const float*)d_in[0];
    const int* targs    = (const int*)d_in[1];
    float* out = (float*)d_out;

    uint32_t *keysA, *keysB;
    unsigned char* temp;
    double* lossp;
    cudaGetSymbolAddress((void**)&keysA, g_keysA);
    cudaGetSymbolAddress((void**)&keysB, g_keysB);
    cudaGetSymbolAddress((void**)&temp,  g_sort_temp);
    cudaGetSymbolAddress((void**)&lossp, g_loss);

    cudaMemsetAsync(lossp, 0, sizeof(double), 0);

    build_keys_kernel<<<P_PIX / 256, 256>>>(logits, targs, keysA);

    cub::DoubleBuffer<uint32_t> dk(keysA, keysB);
    size_t req = 0;
    cub::DeviceRadixSort::SortKeysDescending(nullptr, req, dk, TOTAL, 0, 32,
                                             (cudaStream_t)0);
    if (req > (size_t)(64u << 20)) req = (size_t)(64u << 20); // never expected
    cub::DeviceRadixSort::SortKeysDescending(temp, req, dk, TOTAL, 0, 32,
                                             (cudaStream_t)0);
    const uint32_t* sorted = dk.Current();

    tile_sums_kernel<<<NUM_TILES, 256>>>(sorted);
    scan_tiles_kernel<<<C_CLS, 256>>>();
    loss_kernel<<<NUM_TILES, 256>>>(sorted);
    finalize_kernel<<<1, 1>>>(out);
}

// round 3
// speedup vs baseline: 2.5919x; 2.5919x over previous
#include <cuda_runtime.h>
#include <cstdint>
#include <cub/cub.cuh>

// Problem constants (fixed shapes from reference)
#define B_BATCH 4
#define C_CLS   19
#define HW      (512 * 512)            // 262144
#define P_PIX   (B_BATCH * HW)         // 1048576

// Quantization: err in [0,1] -> fp32 bits in [0, 0x3F800000]; bits 31,30 are
// always 0, so bits[29:12] (18 bits: 7 exponent + 11 mantissa) are a monotone
// 18-bit key. Within-bucket relative spread 2^-11; midpoint dequantization
// error <= 2^-12 ~ 1.2e-4 absolute. Lovasz extension is 1-Lipschitz in l_inf
// (all d_i >= 0, sum d_i = J_final <= 1) -> loss perturbation <= 1.2e-4.
#define QBITS 18
#define NB_PER_CLASS (1 << QBITS)          // 262144
#define QMASK (NB_PER_CLASS - 1)
#define NB (C_CLS * NB_PER_CLASS)          // 4,980,736 buckets

// Scratch (__device__ globals; no allocation allowed in kernel_launch)
__device__ __align__(16) unsigned long long g_hist[NB];  // packed: cnt | gt<<32
__device__ __align__(16) unsigned long long g_scan[NB];  // exclusive prefix
__device__ __align__(16) unsigned char g_scan_temp[16u << 20];
__device__ uint32_t g_baseCnt[C_CLS];
__device__ uint32_t g_baseGt[C_CLS];
__device__ uint32_t g_nC[C_CLS];
__device__ double   g_loss;

// ---------------------------------------------------------------------------
// Kernel 1: fused softmax + histogram build. One thread per pixel; for each of
// the 19 classes, quantize |fg - p| to an 18-bit log-spaced bucket and do ONE
// packed u64 atomicAdd carrying (count += 1, gt += gt).
// Bucket index is descending-error order: qd = QMASK - q.
// NOTE: targets are int32 on device (JAX x64 disabled).
// ---------------------------------------------------------------------------
__global__ void build_hist_kernel(const float* __restrict__ logits,
                                  const int* __restrict__ targets) {
    int p = blockIdx.x * blockDim.x + threadIdx.x;
    if (p >= P_PIX) return;
    int b  = p >> 18;          // p / HW
    int hw = p & (HW - 1);
    const float* base = logits + (size_t)b * C_CLS * HW + hw;

    float l[C_CLS];
    float m = -1e30f;
#pragma unroll
    for (int c = 0; c < C_CLS; c++) {
        l[c] = base[(size_t)c * HW];
        m = fmaxf(m, l[c]);
    }
    float s = 0.0f;
#pragma unroll
    for (int c = 0; c < C_CLS; c++) {
        l[c] = __expf(l[c] - m);
        s += l[c];
    }
    float inv = 1.0f / s;
    int t = targets[p];
#pragma unroll
    for (int c = 0; c < C_CLS; c++) {
        float pr = l[c] * inv;
        unsigned long long gt = (t == c) ? 1ull : 0ull;
        float err = gt ? (1.0f - pr) : pr;
        err = fmaxf(err, 0.0f);                      // guard 1-ulp overshoot
        uint32_t q = __float_as_uint(err) >> 12;     // 18-bit monotone key
        uint32_t idx = ((uint32_t)c << QBITS) | (QMASK - q);
        atomicAdd(&g_hist[idx], 1ull | (gt << 32));
    }
}

// ---------------------------------------------------------------------------
// Kernel 2 (after global exclusive scan): per-class bases and gt totals.
// ---------------------------------------------------------------------------
__global__ void class_totals_kernel() {
    int c = threadIdx.x;
    if (c >= C_CLS) return;
    unsigned long long base = g_scan[c << QBITS];
    int last = ((c + 1) << QBITS) - 1;
    unsigned long long endS = g_scan[last];
    unsigned long long endH = g_hist[last];
    g_baseCnt[c] = (uint32_t)base;
    g_baseGt[c]  = (uint32_t)(base >> 32);
    g_nC[c] = (uint32_t)((endS >> 32) + (endH >> 32) - (base >> 32));
}

// ---------------------------------------------------------------------------
// Kernel 3: per-bucket Lovasz contribution.
// All elements in a bucket share e -> contribution telescopes exactly:
//   e * (J(p1, cs1) - J(p0, cs0)),  J(p, cs) = p / (n + p - cs),  J(0,.) = 0.
// J-difference with exact int64 numerator (cancellation-free); float divide.
// Handles n==0 automatically (first nonempty bucket gets e*1, rest 0).
// ---------------------------------------------------------------------------
__global__ void eval_kernel() {
    int idx0 = (blockIdx.x * blockDim.x + threadIdx.x) * 4;
    double acc = 0.0;
#pragma unroll
    for (int j = 0; j < 4; j++) {
        int bk = idx0 + j;
        unsigned long long h = g_hist[bk];
        if (h == 0ull) continue;
        uint32_t mcnt = (uint32_t)h;
        uint32_t g    = (uint32_t)(h >> 32);
        unsigned long long sv = g_scan[bk];
        uint32_t c   = (uint32_t)bk >> QBITS;
        uint32_t r0  = (uint32_t)sv - g_baseCnt[c];
        uint32_t cs0 = (uint32_t)(sv >> 32) - g_baseGt[c];
        uint32_t n   = g_nC[c];
        uint32_t p1  = r0 + mcnt;
        uint32_t cs1 = cs0 + g;

        float diff;
        if (r0 == 0u) {
            diff = (float)p1 / (float)(n + p1 - cs1);
        } else {
            long long num = (long long)p1 * (long long)(n + r0 - cs0)
                          - (long long)r0 * (long long)(n + p1 - cs1);
            float den = (float)((double)(n + p1 - cs1) * (double)(n + r0 - cs0));
            diff = (float)num / den;
        }
        uint32_t q = QMASK - ((uint32_t)bk & QMASK);
        float e = __uint_as_float((q << 12) | 0x800u);   // bucket midpoint
        acc += (double)e * (double)diff;
    }

    __shared__ double red[256];
    red[threadIdx.x] = acc;
    __syncthreads();
#pragma unroll
    for (int o = 128; o > 0; o >>= 1) {
        if (threadIdx.x < o) red[threadIdx.x] += red[threadIdx.x + o];
        __syncthreads();
    }
    if (threadIdx.x == 0) atomicAdd(&g_loss, red[0]);
}

__global__ void finalize_kernel(float* __restrict__ out) {
    out[0] = (float)(g_loss / (double)C_CLS);
}

// ---------------------------------------------------------------------------
// Host launcher (graph-capturable; no allocation, no sync)
// ---------------------------------------------------------------------------
extern "C" void kernel_launch(void* const* d_in, const int* in_sizes, int n_in,
                              void* d_out, int out_size) {
    const float* logits = (const float*)d_in[0];
    const int* targs    = (const int*)d_in[1];
    float* out = (float*)d_out;

    unsigned long long *hist, *scan;
    unsigned char* temp;
    double* lossp;
    cudaGetSymbolAddress((void**)&hist,  g_hist);
    cudaGetSymbolAddress((void**)&scan,  g_scan);
    cudaGetSymbolAddress((void**)&temp,  g_scan_temp);
    cudaGetSymbolAddress((void**)&lossp, g_loss);

    cudaMemsetAsync(hist, 0, (size_t)NB * sizeof(unsigned long long), 0);
    cudaMemsetAsync(lossp, 0, sizeof(double), 0);

    build_hist_kernel<<<P_PIX / 256, 256>>>(logits, targs);

    size_t req = 0;
    cub::DeviceScan::ExclusiveSum(nullptr, req, hist, scan, NB, (cudaStream_t)0);
    if (req > (size_t)(16u << 20)) req = (size_t)(16u << 20);  // never expected
    cub::DeviceScan::ExclusiveSum(temp, req, hist, scan, NB, (cudaStream_t)0);

    class_totals_kernel<<<1, 32>>>();
    eval_kernel<<<NB / 1024, 256>>>();   // 4864 blocks * 256 thr * 4 buckets
    finalize_kernel<<<1, 1>>>(out);
}